// round 2
// baseline (speedup 1.0000x reference)
#include <cuda_runtime.h>
#include <math.h>

#define BB 8
#define IMG 256
#define INCH 2
#define PSZ 16
#define EE 256
#define DEPTH 8
#define HPN 16
#define LL 256
#define DI 512
#define DS 16
#define DTRN 16
#define DCN 4
#define NTOK 2048          // B*L
#define XZW 1024           // 2*DI

// ---------------- scratch ----------------
__device__ float g_temb[BB*EE];
__device__ float g_h[NTOK*EE];
__device__ float g_hn[NTOK*EE];
__device__ float g_patches[NTOK*512];
__device__ float g_xz[NTOK*XZW];
__device__ float g_u[NTOK*DI];
__device__ float g_dbc[NTOK*48];
__device__ float g_dt[NTOK*DI];
__device__ float g_y[NTOK*DI];
__device__ float g_feat[BB*EE*HPN*HPN];
__device__ float g_d1[BB*128*32*32];
__device__ float g_d2[BB*64*64*64];
__device__ float g_d3[BB*32*128*128];

__device__ __forceinline__ float geluf(float v){ return 0.5f*v*(1.0f+erff(v*0.70710678118654752f)); }
__device__ __forceinline__ float siluf(float v){ return v/(1.0f+__expf(-v)); }

// ---------------- time embedding ----------------
__global__ void time_emb_kernel(const int* __restrict__ t, const float* __restrict__ w1,
                                const float* __restrict__ b1, const float* __restrict__ w2,
                                const float* __restrict__ b2){
  __shared__ float hdn[EE];
  int b = blockIdx.x; int j = threadIdx.x;
  float tf = (float)t[b];
  hdn[j] = geluf(tf*w1[j] + b1[j]);
  __syncthreads();
  float acc = b2[j];
  #pragma unroll 8
  for (int k=0;k<EE;k++) acc = fmaf(hdn[k], w2[k*EE + j], acc);
  g_temb[b*EE + j] = acc;
}

// ---------------- im2col patch gather ----------------
__global__ void patch_gather_kernel(const float* __restrict__ x){
  int idx = blockIdx.x*blockDim.x + threadIdx.x;
  int k = idx & 511; int tok = idx >> 9;
  int l = tok & (LL-1); int b = tok >> 8;
  int c = k >> 8; int rem = k & 255; int p = rem >> 4; int q = rem & 15;
  int hp = l >> 4; int wp = l & 15;
  g_patches[idx] = x[(((size_t)(b*INCH + c))*IMG + hp*PSZ + p)*IMG + wp*PSZ + q];
}

// ---------------- double-buffered SGEMM: C = A * Bw^T (+epilogues) ----------------
// A: [M,K] row-major, Bw: [N,K] row-major. Requires M%BM==0, N%BN==0, K%BK==0.
// EPI: 0 = (+bias if non-null); 1 = +bias +pos[l,n] +temb[b,n] (N==256, m=(b,l));
//      2 = +aux[m,n] (residual)
template<int BM,int BN,int BK,int TM,int TN,int EPI>
__global__ void sgemm_kernel(const float* __restrict__ A, const float* __restrict__ Bw,
                             const float* __restrict__ bias, const float* __restrict__ aux,
                             const float* __restrict__ temb,
                             float* __restrict__ Cc, int M, int N, int K)
{
  constexpr int THREADS = (BM/TM)*(BN/TN);
  constexpr int RSTRIDE = THREADS/4;
  constexpr int F4A = BM*BK/(4*THREADS);
  constexpr int F4B = BN*BK/(4*THREADS);
  __shared__ float As[2][BK][BM];
  __shared__ float Bs[2][BK][BN];
  const int tid = threadIdx.x;
  const int m0 = blockIdx.y*BM, n0 = blockIdx.x*BN;
  const int tx = tid % (BN/TN), ty = tid / (BN/TN);
  const int lr = tid >> 2, lc = (tid & 3) << 2;
  const float* Ab = A + (size_t)m0*K + lc;
  const float* Bb = Bw + (size_t)n0*K + lc;
  float acc[TM][TN] = {};
  float4 ra[F4A], rb[F4B];

  // preload tile 0
  #pragma unroll
  for (int i=0;i<F4A;i++){
    int r = lr + i*RSTRIDE;
    float4 v = *(const float4*)(Ab + (size_t)r*K);
    As[0][lc+0][r]=v.x; As[0][lc+1][r]=v.y; As[0][lc+2][r]=v.z; As[0][lc+3][r]=v.w;
  }
  #pragma unroll
  for (int i=0;i<F4B;i++){
    int r = lr + i*RSTRIDE;
    float4 v = *(const float4*)(Bb + (size_t)r*K);
    Bs[0][lc+0][r]=v.x; Bs[0][lc+1][r]=v.y; Bs[0][lc+2][r]=v.z; Bs[0][lc+3][r]=v.w;
  }
  __syncthreads();

  const int NT = K/BK;
  for (int t=0;t<NT;t++){
    const int buf = t&1;
    if (t+1<NT){
      #pragma unroll
      for (int i=0;i<F4A;i++) ra[i] = *(const float4*)(Ab + (size_t)(lr+i*RSTRIDE)*K + (t+1)*BK);
      #pragma unroll
      for (int i=0;i<F4B;i++) rb[i] = *(const float4*)(Bb + (size_t)(lr+i*RSTRIDE)*K + (t+1)*BK);
    }
    #pragma unroll
    for (int k=0;k<BK;k++){
      float av[TM], bv[TN];
      #pragma unroll
      for (int i=0;i<TM/4;i++){
        float4 v = *(const float4*)&As[buf][k][ty*TM + i*4];
        av[i*4]=v.x; av[i*4+1]=v.y; av[i*4+2]=v.z; av[i*4+3]=v.w;
      }
      #pragma unroll
      for (int j=0;j<TN/4;j++){
        float4 v = *(const float4*)&Bs[buf][k][tx*TN + j*4];
        bv[j*4]=v.x; bv[j*4+1]=v.y; bv[j*4+2]=v.z; bv[j*4+3]=v.w;
      }
      #pragma unroll
      for (int i=0;i<TM;i++)
        #pragma unroll
        for (int j=0;j<TN;j++) acc[i][j] = fmaf(av[i], bv[j], acc[i][j]);
    }
    if (t+1<NT){
      #pragma unroll
      for (int i=0;i<F4A;i++){
        int r = lr + i*RSTRIDE;
        As[buf^1][lc+0][r]=ra[i].x; As[buf^1][lc+1][r]=ra[i].y; As[buf^1][lc+2][r]=ra[i].z; As[buf^1][lc+3][r]=ra[i].w;
      }
      #pragma unroll
      for (int i=0;i<F4B;i++){
        int r = lr + i*RSTRIDE;
        Bs[buf^1][lc+0][r]=rb[i].x; Bs[buf^1][lc+1][r]=rb[i].y; Bs[buf^1][lc+2][r]=rb[i].z; Bs[buf^1][lc+3][r]=rb[i].w;
      }
    }
    __syncthreads();
  }

  #pragma unroll
  for (int i=0;i<TM;i++){
    int gm = m0 + ty*TM + i;
    #pragma unroll
    for (int j=0;j<TN;j+=4){
      int gn = n0 + tx*TN + j;
      float4 v = make_float4(acc[i][j],acc[i][j+1],acc[i][j+2],acc[i][j+3]);
      if (EPI==0){
        if (bias){ float4 b4 = *(const float4*)(bias+gn); v.x+=b4.x; v.y+=b4.y; v.z+=b4.z; v.w+=b4.w; }
      } else if (EPI==1){
        float4 b4 = *(const float4*)(bias+gn);
        float4 p4 = *(const float4*)(aux + (size_t)(gm & 255)*EE + gn);
        float4 t4 = *(const float4*)(temb + (size_t)(gm >> 8)*EE + gn);
        v.x += b4.x+p4.x+t4.x; v.y += b4.y+p4.y+t4.y; v.z += b4.z+p4.z+t4.z; v.w += b4.w+p4.w+t4.w;
      } else {
        float4 a4 = *(const float4*)(aux + (size_t)gm*N + gn);
        v.x+=a4.x; v.y+=a4.y; v.z+=a4.z; v.w+=a4.w;
      }
      *(float4*)(Cc + (size_t)gm*N + gn) = v;
    }
  }
}

// ---------------- LayerNorm ----------------
__global__ void ln_kernel(const float* __restrict__ g, const float* __restrict__ bta){
  __shared__ float ss[8], ssq[8], mv[2];
  int tok = blockIdx.x;
  float v = g_h[(size_t)tok*EE + threadIdx.x];
  float s = v, sq = v*v;
  #pragma unroll
  for (int m=16;m;m>>=1){ s += __shfl_xor_sync(0xffffffffu, s, m); sq += __shfl_xor_sync(0xffffffffu, sq, m); }
  int w = threadIdx.x >> 5;
  if ((threadIdx.x & 31) == 0){ ss[w]=s; ssq[w]=sq; }
  __syncthreads();
  if (threadIdx.x == 0){
    float a=0.f, bq=0.f;
    #pragma unroll
    for (int i=0;i<8;i++){ a+=ss[i]; bq+=ssq[i]; }
    float mean = a*(1.f/EE);
    float var  = bq*(1.f/EE) - mean*mean;
    mv[0]=mean; mv[1]=rsqrtf(var + 1e-5f);
  }
  __syncthreads();
  g_hn[(size_t)tok*EE + threadIdx.x] = (v - mv[0])*mv[1]*g[threadIdx.x] + bta[threadIdx.x];
}

// ---------------- causal conv + SiLU; also zeroes g_dbc for split-K ----------------
__global__ void conv_silu_kernel(const float* __restrict__ w, const float* __restrict__ bias){
  int idx = blockIdx.x*blockDim.x + threadIdx.x;  // NTOK*DI
  if (idx < NTOK*48/4){
    ((float4*)g_dbc)[idx] = make_float4(0.f,0.f,0.f,0.f);
  }
  int d = idx & (DI-1); int tok = idx >> 9; int l = tok & 255; int b = tok >> 8;
  float acc = bias[d];
  #pragma unroll
  for (int j=0;j<DCN;j++){
    int ls = l + j - (DCN-1);
    if (ls >= 0) acc = fmaf(g_xz[((size_t)(b*LL + ls))*XZW + d], w[d*DCN + j], acc);
  }
  g_u[idx] = siluf(acc);
}

// ---------------- x_proj: dbc[M=2048,48] += U[M,512] @ W[48,512]^T  (split-K=4) ----
__global__ void xproj_kernel(const float* __restrict__ U, const float* __restrict__ W){
  __shared__ float As[64][65];
  __shared__ float Bs[64][48];
  int tid = threadIdx.x;
  int m0 = blockIdx.x*64;
  int k0base = blockIdx.y*128;
  int m = tid>>2, ng = tid&3;
  float acc[12] = {};
  for (int kc=0; kc<128; kc+=64){
    int k0 = k0base + kc;
    int lrr = tid>>4, lcc = (tid&15)<<2;
    #pragma unroll
    for (int i=0;i<4;i++){
      int r = lrr + i*16;
      float4 v = *(const float4*)(U + (size_t)(m0+r)*DI + k0 + lcc);
      As[lcc+0][r]=v.x; As[lcc+1][r]=v.y; As[lcc+2][r]=v.z; As[lcc+3][r]=v.w;
    }
    #pragma unroll
    for (int i=0;i<3;i++){
      int f = tid + i*256;            // 0..767
      int row = f>>4, c4 = (f&15)<<2;
      float4 v = *(const float4*)(W + (size_t)row*DI + k0 + c4);
      Bs[c4+0][row]=v.x; Bs[c4+1][row]=v.y; Bs[c4+2][row]=v.z; Bs[c4+3][row]=v.w;
    }
    __syncthreads();
    #pragma unroll
    for (int k=0;k<64;k++){
      float a = As[k][m];
      float4 b0 = *(const float4*)&Bs[k][ng*12];
      float4 b1 = *(const float4*)&Bs[k][ng*12+4];
      float4 b2 = *(const float4*)&Bs[k][ng*12+8];
      acc[0]=fmaf(a,b0.x,acc[0]); acc[1]=fmaf(a,b0.y,acc[1]); acc[2]=fmaf(a,b0.z,acc[2]); acc[3]=fmaf(a,b0.w,acc[3]);
      acc[4]=fmaf(a,b1.x,acc[4]); acc[5]=fmaf(a,b1.y,acc[5]); acc[6]=fmaf(a,b1.z,acc[6]); acc[7]=fmaf(a,b1.w,acc[7]);
      acc[8]=fmaf(a,b2.x,acc[8]); acc[9]=fmaf(a,b2.y,acc[9]); acc[10]=fmaf(a,b2.z,acc[10]); acc[11]=fmaf(a,b2.w,acc[11]);
    }
    __syncthreads();
  }
  float* op = g_dbc + (size_t)(m0+m)*48 + ng*12;
  #pragma unroll
  for (int j=0;j<12;j++) atomicAdd(op+j, acc[j]);
}

// ---------------- dt = softplus(dbc[:, :16] @ dt_w^T + dt_b) ----------------
__global__ void dt_kernel(const float* __restrict__ dtw, const float* __restrict__ dtb){
  int idx = blockIdx.x*blockDim.x + threadIdx.x;  // NTOK*DI
  int d = idx & (DI-1); int tok = idx >> 9;
  const float* db = &g_dbc[(size_t)tok*48];
  float acc = dtb[d];
  #pragma unroll
  for (int r=0;r<DTRN;r++) acc = fmaf(db[r], dtw[d*DTRN + r], acc);
  g_dt[idx] = (acc > 20.f) ? acc : log1pf(__expf(acc));
}

// ---------------- SSM scan (+ fused D-skip and output gating) ----------------
__global__ void ssm_kernel(const float* __restrict__ Alog, const float* __restrict__ Dp){
  int s = threadIdx.x & 15;
  int hw = threadIdx.x >> 4;
  int pair = blockIdx.x*8 + hw;
  int d = pair & (DI-1); int b = pair >> 9;
  float As = -__expf(Alog[d*DS + s]);
  float Dv = Dp[d];
  float hst = 0.f;
  const float* ub   = g_u   + (size_t)b*LL*DI + d;
  const float* dtb  = g_dt  + (size_t)b*LL*DI + d;
  const float* dbcb = g_dbc + (size_t)b*LL*48;
  const float* zb   = g_xz  + (size_t)b*LL*XZW + DI + d;
  float* yb = g_y + (size_t)b*LL*DI + d;
  for (int tt=0; tt<LL; tt++){
    float delta = dtb[(size_t)tt*DI];
    float uv    = ub[(size_t)tt*DI];
    float Bm = dbcb[tt*48 + DTRN + s];
    float Cm = dbcb[tt*48 + DTRN + DS + s];
    hst = fmaf(__expf(delta*As), hst, (delta*uv)*Bm);
    float val = hst*Cm;
    val += __shfl_xor_sync(0xffffffffu, val, 8, 16);
    val += __shfl_xor_sync(0xffffffffu, val, 4, 16);
    val += __shfl_xor_sync(0xffffffffu, val, 2, 16);
    val += __shfl_xor_sync(0xffffffffu, val, 1, 16);
    if (s == 0){
      float z = zb[(size_t)tt*XZW];
      float yv = val + uv*Dv;
      yb[(size_t)tt*DI] = yv * (z/(1.f+__expf(-z)));
    }
  }
}

// ---------------- feat[b,e,l] = h[b,l,e]  (smem transpose) ----------------
__global__ void feat_kernel(){
  __shared__ float tile[32][33];
  int b = blockIdx.z; int t0 = blockIdx.x*32; int e0 = blockIdx.y*32;
  int tx = threadIdx.x, ty = threadIdx.y;  // 32 x 8
  #pragma unroll
  for (int i=0;i<32;i+=8)
    tile[ty+i][tx] = g_h[((size_t)b*LL + t0+ty+i)*EE + e0+tx];
  __syncthreads();
  #pragma unroll
  for (int i=0;i<32;i+=8)
    g_feat[((size_t)b*EE + e0+ty+i)*LL + t0+tx] = tile[tx][ty+i];
}

// ---------------- ConvTranspose2d stride2 k2: OGRP out-channels x 4 pq per thread ----
template<int C,int O,int OGRP,int GELU>
__global__ void convt_kernel(const float* __restrict__ x, const float* __restrict__ w,
                             const float* __restrict__ bias, float* __restrict__ out,
                             int Hin, int Win){
  int idx = blockIdx.x*blockDim.x + threadIdx.x;
  int w_ = idx % Win; int tmp = idx / Win;
  int h_ = tmp % Hin; tmp /= Hin;
  int og = tmp % (O/OGRP); int b = tmp / (O/OGRP);
  int o0 = og*OGRP;
  float acc[OGRP][4];
  #pragma unroll
  for (int g=0;g<OGRP;g++){
    float bv = bias[o0+g];
    acc[g][0]=bv; acc[g][1]=bv; acc[g][2]=bv; acc[g][3]=bv;
  }
  const float* xp = x + ((size_t)b*C*Hin + h_)*Win + w_;
  const float* wp = w + o0*4;
  size_t xstride = (size_t)Hin*Win;
  #pragma unroll 4
  for (int c=0;c<C;c++){
    float xv = __ldg(xp + c*xstride);
    const float4* w4 = (const float4*)(wp + (size_t)c*O*4);
    #pragma unroll
    for (int g=0;g<OGRP;g++){
      float4 wt = __ldg(w4 + g);
      acc[g][0]=fmaf(xv,wt.x,acc[g][0]); acc[g][1]=fmaf(xv,wt.y,acc[g][1]);
      acc[g][2]=fmaf(xv,wt.z,acc[g][2]); acc[g][3]=fmaf(xv,wt.w,acc[g][3]);
    }
  }
  int Ho = 2*Hin, Wo = 2*Win;
  #pragma unroll
  for (int g=0;g<OGRP;g++){
    float r00=acc[g][0], r01=acc[g][1], r10=acc[g][2], r11=acc[g][3];
    if (GELU){ r00=geluf(r00); r01=geluf(r01); r10=geluf(r10); r11=geluf(r11); }
    float* op = out + (((size_t)b*O + o0+g)*Ho + 2*h_)*(size_t)Wo + 2*w_;
    *(float2*)op        = make_float2(r00,r01);
    *(float2*)(op + Wo) = make_float2(r10,r11);
  }
}

// ---------------- launch ----------------
extern "C" void kernel_launch(void* const* d_in, const int* in_sizes, int n_in,
                              void* d_out, int out_size){
  const float* x       = (const float*)d_in[0];
  const int*   t       = (const int*)d_in[1];
  const float* time_w1 = (const float*)d_in[2];
  const float* time_b1 = (const float*)d_in[3];
  const float* time_w2 = (const float*)d_in[4];
  const float* time_b2 = (const float*)d_in[5];
  const float* patch_w = (const float*)d_in[6];
  const float* patch_b = (const float*)d_in[7];
  const float* pos     = (const float*)d_in[8];
  const float* ln_g    = (const float*)d_in[9];
  const float* ln_b    = (const float*)d_in[10];
  const float* in_proj = (const float*)d_in[11];
  const float* conv_w  = (const float*)d_in[12];
  const float* conv_b  = (const float*)d_in[13];
  const float* x_proj  = (const float*)d_in[14];
  const float* dt_w    = (const float*)d_in[15];
  const float* dt_b    = (const float*)d_in[16];
  const float* A_log   = (const float*)d_in[17];
  const float* Dp      = (const float*)d_in[18];
  const float* out_proj= (const float*)d_in[19];
  const float* dw1 = (const float*)d_in[20];
  const float* db1 = (const float*)d_in[21];
  const float* dw2 = (const float*)d_in[22];
  const float* db2 = (const float*)d_in[23];
  const float* dw3 = (const float*)d_in[24];
  const float* db3 = (const float*)d_in[25];
  const float* dw4 = (const float*)d_in[26];
  const float* db4 = (const float*)d_in[27];

  float *p_patches,*p_h,*p_hn,*p_xz,*p_u,*p_y,*p_temb,*p_feat,*p_d1,*p_d2,*p_d3;
  cudaGetSymbolAddress((void**)&p_patches, g_patches);
  cudaGetSymbolAddress((void**)&p_h, g_h);
  cudaGetSymbolAddress((void**)&p_hn, g_hn);
  cudaGetSymbolAddress((void**)&p_xz, g_xz);
  cudaGetSymbolAddress((void**)&p_u, g_u);
  cudaGetSymbolAddress((void**)&p_y, g_y);
  cudaGetSymbolAddress((void**)&p_temb, g_temb);
  cudaGetSymbolAddress((void**)&p_feat, g_feat);
  cudaGetSymbolAddress((void**)&p_d1, g_d1);
  cudaGetSymbolAddress((void**)&p_d2, g_d2);
  cudaGetSymbolAddress((void**)&p_d3, g_d3);

  time_emb_kernel<<<BB, EE>>>(t, time_w1, time_b1, time_w2, time_b2);
  patch_gather_kernel<<<(NTOK*512)/256, 256>>>(x);
  // patch embed: 2048x256x512, epilogue = bias + pos + temb
  sgemm_kernel<64,64,16,4,8,1><<<dim3(EE/64, NTOK/64), 128>>>(
      p_patches, patch_w, patch_b, pos, p_temb, p_h, NTOK, EE, 512);

  for (int i=0;i<DEPTH;i++){
    ln_kernel<<<NTOK, EE>>>(ln_g + (size_t)i*EE, ln_b + (size_t)i*EE);
    sgemm_kernel<128,128,16,8,8,0><<<dim3(XZW/128, NTOK/128), 256>>>(
        p_hn, in_proj + (size_t)i*XZW*EE, nullptr, nullptr, nullptr, p_xz, NTOK, XZW, EE);
    conv_silu_kernel<<<(NTOK*DI)/256, 256>>>(conv_w + (size_t)i*DI*DCN, conv_b + (size_t)i*DI);
    xproj_kernel<<<dim3(NTOK/64, 4), 256>>>(p_u, x_proj + (size_t)i*48*DI);
    dt_kernel<<<(NTOK*DI)/256, 256>>>(dt_w + (size_t)i*DI*DTRN, dt_b + (size_t)i*DI);
    ssm_kernel<<<(BB*DI)/8, 128>>>(A_log + (size_t)i*DI*DS, Dp + (size_t)i*DI);
    sgemm_kernel<64,64,16,4,8,2><<<dim3(EE/64, NTOK/64), 128>>>(
        p_y, out_proj + (size_t)i*EE*DI, nullptr, p_h, nullptr, p_h, NTOK, EE, DI);
  }

  feat_kernel<<<dim3(LL/32, EE/32, BB), dim3(32,8)>>>();
  convt_kernel<256,128,4,1><<<(BB*(128/4)*16*16)/256, 256>>>(p_feat, dw1, db1, p_d1, 16, 16);
  convt_kernel<128,64,4,1><<<(BB*(64/4)*32*32)/256, 256>>>(p_d1, dw2, db2, p_d2, 32, 32);
  convt_kernel<64,32,4,1><<<(BB*(32/4)*64*64)/256, 256>>>(p_d2, dw3, db3, p_d3, 64, 64);
  convt_kernel<32,1,1,0><<<(BB*1*128*128)/256, 256>>>(p_d3, dw4, db4, (float*)d_out, 128, 128);
}

// round 3
// speedup vs baseline: 1.9618x; 1.9618x over previous
#include <cuda_runtime.h>
#include <math.h>

#define BB 8
#define IMG 256
#define INCH 2
#define PSZ 16
#define EE 256
#define DEPTH 8
#define HPN 16
#define LL 256
#define DI 512
#define DS 16
#define DTRN 16
#define DCN 4
#define NTOK 2048          // B*L
#define XZW 1024           // 2*DI

// ---------------- scratch ----------------
__device__ float g_temb[BB*EE];
__device__ float g_h[NTOK*EE];
__device__ float g_patches[NTOK*512];
__device__ float g_xz[NTOK*XZW];
__device__ float g_ut[BB*DI*LL];    // u transposed [b][d][t]
__device__ float g_dtt[BB*DI*LL];   // dt transposed [b][d][t]
__device__ float g_zs[BB*DI*LL];    // silu(z) transposed [b][d][t]
__device__ float g_bc[NTOK*32];     // B[16],C[16] per token
__device__ float g_yt[BB*DI*LL];    // y transposed [b][d][t]
__device__ float g_feat[BB*EE*HPN*HPN];
__device__ float g_d1[BB*128*32*32];
__device__ float g_d2[BB*64*64*64];
__device__ float g_d3[BB*32*128*128];

__device__ __forceinline__ float geluf(float v){ return 0.5f*v*(1.0f+erff(v*0.70710678118654752f)); }
__device__ __forceinline__ float siluf(float v){ return v/(1.0f+__expf(-v)); }

// ---------------- time embedding ----------------
__global__ void time_emb_kernel(const int* __restrict__ t, const float* __restrict__ w1,
                                const float* __restrict__ b1, const float* __restrict__ w2,
                                const float* __restrict__ b2){
  __shared__ float hdn[EE];
  int b = blockIdx.x; int j = threadIdx.x;
  float tf = (float)t[b];
  hdn[j] = geluf(tf*w1[j] + b1[j]);
  __syncthreads();
  float acc = b2[j];
  #pragma unroll 8
  for (int k=0;k<EE;k++) acc = fmaf(hdn[k], w2[k*EE + j], acc);
  g_temb[b*EE + j] = acc;
}

// ---------------- im2col patch gather ----------------
__global__ void patch_gather_kernel(const float* __restrict__ x){
  int idx = blockIdx.x*blockDim.x + threadIdx.x;
  int k = idx & 511; int tok = idx >> 9;
  int l = tok & (LL-1); int b = tok >> 8;
  int c = k >> 8; int rem = k & 255; int p = rem >> 4; int q = rem & 15;
  int hp = l >> 4; int wp = l & 15;
  g_patches[idx] = x[(((size_t)(b*INCH + c))*IMG + hp*PSZ + p)*IMG + wp*PSZ + q];
}

// ---------------- patch-embed GEMM (64x64, epi: bias+pos+temb) ----------------
__global__ void patch_gemm(const float* __restrict__ A, const float* __restrict__ Bw,
                           const float* __restrict__ bias, const float* __restrict__ pos,
                           const float* __restrict__ temb, float* __restrict__ Cc){
  const int K = 512, N = EE;
  __shared__ float As[2][16][64];
  __shared__ float Bs[2][16][64];
  const int tid = threadIdx.x;               // 128
  const int m0 = blockIdx.y*64, n0 = blockIdx.x*64;
  const int tx = tid & 7, ty = tid >> 3;     // TN=8, TM=4
  const int lr = tid >> 2, lc = (tid & 3) << 2;
  const float* Ab = A + (size_t)m0*K + lc;
  const float* Bb = Bw + (size_t)n0*K + lc;
  float acc[4][8] = {};
  float4 ra[2], rb[2];
  #pragma unroll
  for (int i=0;i<2;i++){
    int r = lr + i*32;
    float4 v = *(const float4*)(Ab + (size_t)r*K);
    As[0][lc+0][r]=v.x; As[0][lc+1][r]=v.y; As[0][lc+2][r]=v.z; As[0][lc+3][r]=v.w;
    float4 w = *(const float4*)(Bb + (size_t)r*K);
    Bs[0][lc+0][r]=w.x; Bs[0][lc+1][r]=w.y; Bs[0][lc+2][r]=w.z; Bs[0][lc+3][r]=w.w;
  }
  __syncthreads();
  const int NT = K/16;
  for (int t=0;t<NT;t++){
    const int buf = t&1;
    if (t+1<NT){
      #pragma unroll
      for (int i=0;i<2;i++) ra[i] = *(const float4*)(Ab + (size_t)(lr+i*32)*K + (t+1)*16);
      #pragma unroll
      for (int i=0;i<2;i++) rb[i] = *(const float4*)(Bb + (size_t)(lr+i*32)*K + (t+1)*16);
    }
    #pragma unroll
    for (int k=0;k<16;k++){
      float4 a4 = *(const float4*)&As[buf][k][ty*4];
      float4 b40 = *(const float4*)&Bs[buf][k][tx*8];
      float4 b41 = *(const float4*)&Bs[buf][k][tx*8+4];
      float av[4]={a4.x,a4.y,a4.z,a4.w};
      float bv[8]={b40.x,b40.y,b40.z,b40.w,b41.x,b41.y,b41.z,b41.w};
      #pragma unroll
      for (int i=0;i<4;i++)
        #pragma unroll
        for (int j=0;j<8;j++) acc[i][j] = fmaf(av[i], bv[j], acc[i][j]);
    }
    if (t+1<NT){
      #pragma unroll
      for (int i=0;i<2;i++){
        int r = lr + i*32;
        As[buf^1][lc+0][r]=ra[i].x; As[buf^1][lc+1][r]=ra[i].y; As[buf^1][lc+2][r]=ra[i].z; As[buf^1][lc+3][r]=ra[i].w;
        Bs[buf^1][lc+0][r]=rb[i].x; Bs[buf^1][lc+1][r]=rb[i].y; Bs[buf^1][lc+2][r]=rb[i].z; Bs[buf^1][lc+3][r]=rb[i].w;
      }
    }
    __syncthreads();
  }
  #pragma unroll
  for (int i=0;i<4;i++){
    int gm = m0 + ty*4 + i;
    int l = gm & 255, bidx = gm >> 8;
    #pragma unroll
    for (int j=0;j<8;j+=4){
      int gn = n0 + tx*8 + j;
      float4 v = make_float4(acc[i][j],acc[i][j+1],acc[i][j+2],acc[i][j+3]);
      float4 b4 = *(const float4*)(bias+gn);
      float4 p4 = *(const float4*)(pos + (size_t)l*EE + gn);
      float4 t4 = *(const float4*)(temb + (size_t)bidx*EE + gn);
      v.x += b4.x+p4.x+t4.x; v.y += b4.y+p4.y+t4.y; v.z += b4.z+p4.z+t4.z; v.w += b4.w+p4.w+t4.w;
      *(float4*)(Cc + (size_t)gm*N + gn) = v;
    }
  }
}

// ---------------- in_proj GEMM with fused LayerNorm on A ----------------
// xz[2048,1024] = LN(h)[2048,256] @ W[1024,256]^T
__global__ void inproj_ln_gemm(const float* __restrict__ W,
                               const float* __restrict__ lng, const float* __restrict__ lnb,
                               float* __restrict__ out){
  const int K = 256, N = 1024;
  __shared__ float As[2][16][128];
  __shared__ float Bs[2][16][128];
  __shared__ float s_mu[128], s_rs[128];
  const int tid = threadIdx.x;               // 256
  const int m0 = blockIdx.y*128, n0 = blockIdx.x*128;
  // row stats (LN)
  {
    int r = tid >> 1, hf = tid & 1;
    const float4* row = (const float4*)(g_h + (size_t)(m0 + r)*K + hf*128);
    float s = 0.f, sq = 0.f;
    #pragma unroll
    for (int i=0;i<32;i++){ float4 v = row[i];
      s += v.x+v.y+v.z+v.w; sq += v.x*v.x+v.y*v.y+v.z*v.z+v.w*v.w; }
    s  += __shfl_xor_sync(0xffffffffu, s, 1);
    sq += __shfl_xor_sync(0xffffffffu, sq, 1);
    if (hf == 0){
      float mu = s*(1.f/256.f);
      float var = sq*(1.f/256.f) - mu*mu;
      s_mu[r] = mu; s_rs[r] = rsqrtf(var + 1e-5f);
    }
  }
  __syncthreads();
  const int tx = tid & 15, ty = tid >> 4;    // TN=8, TM=8
  const int lr = tid >> 2, lc = (tid & 3) << 2;
  const float* Bb = W + (size_t)n0*K + lc;
  float acc[8][8] = {};
  float4 ra[2], rb[2];

  // transformed A load
  #pragma unroll
  for (int i=0;i<2;i++){
    int r = lr + i*64;
    float4 v = *(const float4*)(g_h + (size_t)(m0+r)*K + lc);
    float mu = s_mu[r], rs = s_rs[r];
    float4 g4 = *(const float4*)(lng + lc);
    float4 b4 = *(const float4*)(lnb + lc);
    As[0][lc+0][r]=(v.x-mu)*rs*g4.x+b4.x; As[0][lc+1][r]=(v.y-mu)*rs*g4.y+b4.y;
    As[0][lc+2][r]=(v.z-mu)*rs*g4.z+b4.z; As[0][lc+3][r]=(v.w-mu)*rs*g4.w+b4.w;
    float4 w = *(const float4*)(Bb + (size_t)r*K);
    Bs[0][lc+0][r]=w.x; Bs[0][lc+1][r]=w.y; Bs[0][lc+2][r]=w.z; Bs[0][lc+3][r]=w.w;
  }
  __syncthreads();
  const int NT = K/16;
  for (int t=0;t<NT;t++){
    const int buf = t&1;
    if (t+1<NT){
      int kc = (t+1)*16 + lc;
      float4 g4 = *(const float4*)(lng + kc);
      float4 b4 = *(const float4*)(lnb + kc);
      #pragma unroll
      for (int i=0;i<2;i++){
        int r = lr + i*64;
        float4 v = *(const float4*)(g_h + (size_t)(m0+r)*K + kc);
        float mu = s_mu[r], rs = s_rs[r];
        ra[i].x=(v.x-mu)*rs*g4.x+b4.x; ra[i].y=(v.y-mu)*rs*g4.y+b4.y;
        ra[i].z=(v.z-mu)*rs*g4.z+b4.z; ra[i].w=(v.w-mu)*rs*g4.w+b4.w;
        rb[i] = *(const float4*)(Bb + (size_t)r*K + (t+1)*16);
      }
    }
    #pragma unroll
    for (int k=0;k<16;k++){
      float av[8], bv[8];
      #pragma unroll
      for (int i=0;i<2;i++){
        float4 v = *(const float4*)&As[buf][k][ty*8 + i*4];
        av[i*4]=v.x; av[i*4+1]=v.y; av[i*4+2]=v.z; av[i*4+3]=v.w;
        float4 w = *(const float4*)&Bs[buf][k][tx*8 + i*4];
        bv[i*4]=w.x; bv[i*4+1]=w.y; bv[i*4+2]=w.z; bv[i*4+3]=w.w;
      }
      #pragma unroll
      for (int i=0;i<8;i++)
        #pragma unroll
        for (int j=0;j<8;j++) acc[i][j] = fmaf(av[i], bv[j], acc[i][j]);
    }
    if (t+1<NT){
      #pragma unroll
      for (int i=0;i<2;i++){
        int r = lr + i*64;
        As[buf^1][lc+0][r]=ra[i].x; As[buf^1][lc+1][r]=ra[i].y; As[buf^1][lc+2][r]=ra[i].z; As[buf^1][lc+3][r]=ra[i].w;
        Bs[buf^1][lc+0][r]=rb[i].x; Bs[buf^1][lc+1][r]=rb[i].y; Bs[buf^1][lc+2][r]=rb[i].z; Bs[buf^1][lc+3][r]=rb[i].w;
      }
    }
    __syncthreads();
  }
  #pragma unroll
  for (int i=0;i<8;i++){
    int gm = m0 + ty*8 + i;
    #pragma unroll
    for (int j=0;j<8;j+=4){
      int gn = n0 + tx*8 + j;
      *(float4*)(out + (size_t)gm*N + gn) =
        make_float4(acc[i][j],acc[i][j+1],acc[i][j+2],acc[i][j+3]);
    }
  }
}

// ---------------- fused prep: causal-conv+SiLU, z-SiLU, x_proj, dt; transposed stores ----
__global__ void prep_kernel(const float* __restrict__ cw, const float* __restrict__ cb,
                            const float* __restrict__ xw,   // [48][512]
                            const float* __restrict__ dtw,  // [512][16]
                            const float* __restrict__ dtb){ // [512]
  __shared__ float us[8][513];
  __shared__ float pool[48*129];          // reused: zsm[8][516] then Wb[48][129]
  __shared__ float dbc_s[8][52];
  const int tid = threadIdx.x;            // 256
  const int b  = blockIdx.x >> 5;
  const int l0 = (blockIdx.x & 31) * 8;
  float* zsm = pool;
  // (a) conv+silu -> us ; silu(z) -> zsm
  #pragma unroll
  for (int r=0;r<16;r++){
    int idx = r*256 + tid;
    int d  = idx & 511;
    int ti = idx >> 9;
    int l  = l0 + ti;
    float acc = cb[d];
    #pragma unroll
    for (int j=0;j<4;j++){
      int ls = l + j - 3;
      if (ls >= 0) acc = fmaf(g_xz[((size_t)(b*LL + ls))*XZW + d], cw[d*4 + j], acc);
    }
    us[ti][d] = siluf(acc);
    float z = g_xz[((size_t)(b*LL + l))*XZW + DI + d];
    zsm[ti*516 + d] = siluf(z);
  }
  __syncthreads();
  // (b) transposed coalesced stores of u and silu(z)
  #pragma unroll
  for (int rr=0;rr<2;rr++){
    int d = tid + rr*256;
    float4 v0, v1, w0, w1;
    v0.x=us[0][d]; v0.y=us[1][d]; v0.z=us[2][d]; v0.w=us[3][d];
    v1.x=us[4][d]; v1.y=us[5][d]; v1.z=us[6][d]; v1.w=us[7][d];
    w0.x=zsm[0*516+d]; w0.y=zsm[1*516+d]; w0.z=zsm[2*516+d]; w0.w=zsm[3*516+d];
    w1.x=zsm[4*516+d]; w1.y=zsm[5*516+d]; w1.z=zsm[6*516+d]; w1.w=zsm[7*516+d];
    float* up = g_ut + ((size_t)(b*DI + d))*LL + l0;
    *(float4*)up = v0; *(float4*)(up+4) = v1;
    float* zp = g_zs + ((size_t)(b*DI + d))*LL + l0;
    *(float4*)zp = w0; *(float4*)(zp+4) = w1;
  }
  // (c) x_proj: dbc[ti][j] = sum_k us[ti][k] * xw[j][k]
  const int ti = tid >> 5, lane = tid & 31;
  float accA = 0.f, accB = 0.f;
  for (int kt=0;kt<4;kt++){
    __syncthreads();
    #pragma unroll
    for (int i=0;i<6;i++){
      int f = (tid + i*256)*4;
      int j = f >> 7, c = f & 127;
      float4 v = *(const float4*)(xw + (size_t)j*DI + kt*128 + c);
      pool[j*129+c]=v.x; pool[j*129+c+1]=v.y; pool[j*129+c+2]=v.z; pool[j*129+c+3]=v.w;
    }
    __syncthreads();
    #pragma unroll 4
    for (int c=0;c<128;c++){
      float a = us[ti][kt*128 + c];
      accA = fmaf(a, pool[lane*129 + c], accA);
      if (lane < 16) accB = fmaf(a, pool[(32+lane)*129 + c], accB);
    }
  }
  __syncthreads();
  dbc_s[ti][lane] = accA;
  if (lane < 16) dbc_s[ti][32 + lane] = accB;
  __syncthreads();
  // (d) write B,C rows (tok,32)
  {
    int tti = tid >> 5, jj = tid & 31;
    g_bc[((size_t)(b*LL) + l0 + tti)*32 + jj] = dbc_s[tti][16 + jj];
  }
  // (e) dt = softplus(dbc[:, :16] @ dtw^T + dtb) -> us (reuse) -> transposed store
  #pragma unroll
  for (int r=0;r<16;r++){
    int idx = r*256 + tid;
    int d  = idx & 511;
    int ti2 = idx >> 9;
    const float* dbp = dbc_s[ti2];
    const float4* dw4 = (const float4*)(dtw + (size_t)d*16);
    float4 w0 = dw4[0], w1 = dw4[1], w2 = dw4[2], w3 = dw4[3];
    float acc = dtb[d];
    acc=fmaf(dbp[0],w0.x,acc);  acc=fmaf(dbp[1],w0.y,acc);  acc=fmaf(dbp[2],w0.z,acc);  acc=fmaf(dbp[3],w0.w,acc);
    acc=fmaf(dbp[4],w1.x,acc);  acc=fmaf(dbp[5],w1.y,acc);  acc=fmaf(dbp[6],w1.z,acc);  acc=fmaf(dbp[7],w1.w,acc);
    acc=fmaf(dbp[8],w2.x,acc);  acc=fmaf(dbp[9],w2.y,acc);  acc=fmaf(dbp[10],w2.z,acc); acc=fmaf(dbp[11],w2.w,acc);
    acc=fmaf(dbp[12],w3.x,acc); acc=fmaf(dbp[13],w3.y,acc); acc=fmaf(dbp[14],w3.z,acc); acc=fmaf(dbp[15],w3.w,acc);
    us[ti2][d] = (acc > 20.f) ? acc : log1pf(__expf(acc));
  }
  __syncthreads();
  #pragma unroll
  for (int rr=0;rr<2;rr++){
    int d = tid + rr*256;
    float4 v0, v1;
    v0.x=us[0][d]; v0.y=us[1][d]; v0.z=us[2][d]; v0.w=us[3][d];
    v1.x=us[4][d]; v1.y=us[5][d]; v1.z=us[6][d]; v1.w=us[7][d];
    float* dp = g_dtt + ((size_t)(b*DI + d))*LL + l0;
    *(float4*)dp = v0; *(float4*)(dp+4) = v1;
  }
}

// ---------------- SSM chunked parallel scan: block = one (b,d) ----------------
__global__ void ssm_scan(const float* __restrict__ Alog, const float* __restrict__ Dp){
  __shared__ float sA[16][17], sB[16][17], sH[16][17];
  __shared__ float sv[256][17];
  const int bd = blockIdx.x;
  const int b = bd >> 9, d = bd & 511;
  const int tid = threadIdx.x;
  const int c = tid >> 4, s = tid & 15;
  const float As = -__expf(Alog[d*16 + s]);
  const float* dtp = g_dtt + ((size_t)(b*DI + d))*LL + c*16;
  const float* up  = g_ut  + ((size_t)(b*DI + d))*LL + c*16;
  const float* bcp = g_bc + ((size_t)(b*LL + c*16))*32 + s;
  float a[16], bv[16];
  #pragma unroll
  for (int i=0;i<16;i++){
    float dt = dtp[i], u = up[i];
    float Bm = bcp[i*32];
    a[i]  = __expf(dt * As);
    bv[i] = dt * u * Bm;
  }
  float Ap = 1.f, Bf = 0.f;
  #pragma unroll
  for (int i=0;i<16;i++){ Bf = fmaf(a[i], Bf, bv[i]); Ap *= a[i]; }
  sA[c][s] = Ap; sB[c][s] = Bf;
  __syncthreads();
  if (tid < 16){
    float h = 0.f;
    #pragma unroll
    for (int cc=0;cc<16;cc++){
      sH[cc][tid] = h;
      h = fmaf(sA[cc][tid], h, sB[cc][tid]);
    }
  }
  __syncthreads();
  float h = sH[c][s];
  #pragma unroll
  for (int i=0;i<16;i++){
    h = fmaf(a[i], h, bv[i]);
    float Cm = bcp[i*32 + 16];
    sv[c*16 + i][s] = h * Cm;
  }
  __syncthreads();
  float y = 0.f;
  #pragma unroll
  for (int ss=0;ss<16;ss++) y += sv[tid][ss];
  float u_t = g_ut[((size_t)(b*DI + d))*LL + tid];
  float zs  = g_zs[((size_t)(b*DI + d))*LL + tid];
  g_yt[((size_t)(b*DI + d))*LL + tid] = (y + u_t * Dp[d]) * zs;
}

// ---------------- out_proj GEMM: h += yt^T @ W^T  (A transposed layout) ----------------
__global__ void outproj_gemm(const float* __restrict__ W){   // [256][512]
  const int K = DI, N = EE;
  __shared__ float As[2][16][64];
  __shared__ float Bs[2][16][64];
  const int tid = threadIdx.x;              // 128
  const int m0 = blockIdx.y*64, n0 = blockIdx.x*64;
  const int b = m0 >> 8, t0 = m0 & 255;
  const int kk = tid >> 3, mo = (tid & 7) * 8;
  const int lr = tid >> 2, lc = (tid & 3) << 2;
  const float* Abase = g_yt + ((size_t)(b*DI))*LL + t0 + mo;
  const float* Bb = W + (size_t)n0*K + lc;
  const int tx = tid & 7, ty = tid >> 3;    // TN=8, TM=4
  float acc[4][8] = {};
  float4 ra0, ra1, rb[2];
  {
    float4 a0 = *(const float4*)(Abase + (size_t)kk*LL);
    float4 a1 = *(const float4*)(Abase + (size_t)kk*LL + 4);
    *(float4*)&As[0][kk][mo] = a0; *(float4*)&As[0][kk][mo+4] = a1;
    #pragma unroll
    for (int i=0;i<2;i++){
      int r = lr + i*32;
      float4 v = *(const float4*)(Bb + (size_t)r*K);
      Bs[0][lc+0][r]=v.x; Bs[0][lc+1][r]=v.y; Bs[0][lc+2][r]=v.z; Bs[0][lc+3][r]=v.w;
    }
  }
  __syncthreads();
  const int NT = K/16;
  for (int t=0;t<NT;t++){
    const int buf = t&1;
    if (t+1<NT){
      ra0 = *(const float4*)(Abase + (size_t)((t+1)*16+kk)*LL);
      ra1 = *(const float4*)(Abase + (size_t)((t+1)*16+kk)*LL + 4);
      #pragma unroll
      for (int i=0;i<2;i++) rb[i] = *(const float4*)(Bb + (size_t)(lr+i*32)*K + (t+1)*16);
    }
    #pragma unroll
    for (int k=0;k<16;k++){
      float4 a4 = *(const float4*)&As[buf][k][ty*4];
      float4 b40 = *(const float4*)&Bs[buf][k][tx*8];
      float4 b41 = *(const float4*)&Bs[buf][k][tx*8+4];
      float av[4]={a4.x,a4.y,a4.z,a4.w};
      float bw[8]={b40.x,b40.y,b40.z,b40.w,b41.x,b41.y,b41.z,b41.w};
      #pragma unroll
      for (int i=0;i<4;i++)
        #pragma unroll
        for (int j=0;j<8;j++) acc[i][j] = fmaf(av[i], bw[j], acc[i][j]);
    }
    if (t+1<NT){
      *(float4*)&As[buf^1][kk][mo] = ra0; *(float4*)&As[buf^1][kk][mo+4] = ra1;
      #pragma unroll
      for (int i=0;i<2;i++){
        int r = lr + i*32;
        Bs[buf^1][lc+0][r]=rb[i].x; Bs[buf^1][lc+1][r]=rb[i].y; Bs[buf^1][lc+2][r]=rb[i].z; Bs[buf^1][lc+3][r]=rb[i].w;
      }
    }
    __syncthreads();
  }
  #pragma unroll
  for (int i=0;i<4;i++){
    int gm = m0 + ty*4 + i;
    #pragma unroll
    for (int j=0;j<8;j+=4){
      int gn = n0 + tx*8 + j;
      float4 r4 = *(const float4*)(g_h + (size_t)gm*N + gn);
      *(float4*)(g_h + (size_t)gm*N + gn) =
        make_float4(acc[i][j]+r4.x, acc[i][j+1]+r4.y, acc[i][j+2]+r4.z, acc[i][j+3]+r4.w);
    }
  }
}

// ---------------- feat[b,e,l] = h[b,l,e] ----------------
__global__ void feat_kernel(){
  __shared__ float tile[32][33];
  int b = blockIdx.z; int t0 = blockIdx.x*32; int e0 = blockIdx.y*32;
  int tx = threadIdx.x, ty = threadIdx.y;
  #pragma unroll
  for (int i=0;i<32;i+=8)
    tile[ty+i][tx] = g_h[((size_t)b*LL + t0+ty+i)*EE + e0+tx];
  __syncthreads();
  #pragma unroll
  for (int i=0;i<32;i+=8)
    g_feat[((size_t)b*EE + e0+ty+i)*LL + t0+tx] = tile[tx][ty+i];
}

// ---------------- ConvTranspose2d stride2 k2 ----------------
template<int C,int O,int OGRP,int GELU>
__global__ void convt_kernel(const float* __restrict__ x, const float* __restrict__ w,
                             const float* __restrict__ bias, float* __restrict__ out,
                             int Hin, int Win){
  int idx = blockIdx.x*blockDim.x + threadIdx.x;
  int w_ = idx % Win; int tmp = idx / Win;
  int h_ = tmp % Hin; tmp /= Hin;
  int og = tmp % (O/OGRP); int b = tmp / (O/OGRP);
  int o0 = og*OGRP;
  float acc[OGRP][4];
  #pragma unroll
  for (int g=0;g<OGRP;g++){
    float bvv = bias[o0+g];
    acc[g][0]=bvv; acc[g][1]=bvv; acc[g][2]=bvv; acc[g][3]=bvv;
  }
  const float* xp = x + ((size_t)b*C*Hin + h_)*Win + w_;
  const float* wp = w + o0*4;
  size_t xstride = (size_t)Hin*Win;
  #pragma unroll 4
  for (int c=0;c<C;c++){
    float xv = __ldg(xp + c*xstride);
    const float4* w4 = (const float4*)(wp + (size_t)c*O*4);
    #pragma unroll
    for (int g=0;g<OGRP;g++){
      float4 wt = __ldg(w4 + g);
      acc[g][0]=fmaf(xv,wt.x,acc[g][0]); acc[g][1]=fmaf(xv,wt.y,acc[g][1]);
      acc[g][2]=fmaf(xv,wt.z,acc[g][2]); acc[g][3]=fmaf(xv,wt.w,acc[g][3]);
    }
  }
  int Ho = 2*Hin, Wo = 2*Win;
  #pragma unroll
  for (int g=0;g<OGRP;g++){
    float r00=acc[g][0], r01=acc[g][1], r10=acc[g][2], r11=acc[g][3];
    if (GELU){ r00=geluf(r00); r01=geluf(r01); r10=geluf(r10); r11=geluf(r11); }
    float* op = out + (((size_t)b*O + o0+g)*Ho + 2*h_)*(size_t)Wo + 2*w_;
    *(float2*)op        = make_float2(r00,r01);
    *(float2*)(op + Wo) = make_float2(r10,r11);
  }
}

// ---------------- launch ----------------
extern "C" void kernel_launch(void* const* d_in, const int* in_sizes, int n_in,
                              void* d_out, int out_size){
  const float* x       = (const float*)d_in[0];
  const int*   t       = (const int*)d_in[1];
  const float* time_w1 = (const float*)d_in[2];
  const float* time_b1 = (const float*)d_in[3];
  const float* time_w2 = (const float*)d_in[4];
  const float* time_b2 = (const float*)d_in[5];
  const float* patch_w = (const float*)d_in[6];
  const float* patch_b = (const float*)d_in[7];
  const float* pos     = (const float*)d_in[8];
  const float* ln_g    = (const float*)d_in[9];
  const float* ln_b    = (const float*)d_in[10];
  const float* in_proj = (const float*)d_in[11];
  const float* conv_w  = (const float*)d_in[12];
  const float* conv_b  = (const float*)d_in[13];
  const float* x_proj  = (const float*)d_in[14];
  const float* dt_w    = (const float*)d_in[15];
  const float* dt_b    = (const float*)d_in[16];
  const float* A_log   = (const float*)d_in[17];
  const float* Dp      = (const float*)d_in[18];
  const float* out_proj= (const float*)d_in[19];
  const float* dw1 = (const float*)d_in[20];
  const float* db1 = (const float*)d_in[21];
  const float* dw2 = (const float*)d_in[22];
  const float* db2 = (const float*)d_in[23];
  const float* dw3 = (const float*)d_in[24];
  const float* db3 = (const float*)d_in[25];
  const float* dw4 = (const float*)d_in[26];
  const float* db4 = (const float*)d_in[27];

  float *p_patches,*p_h,*p_xz,*p_temb,*p_feat,*p_d1,*p_d2,*p_d3;
  cudaGetSymbolAddress((void**)&p_patches, g_patches);
  cudaGetSymbolAddress((void**)&p_h, g_h);
  cudaGetSymbolAddress((void**)&p_xz, g_xz);
  cudaGetSymbolAddress((void**)&p_temb, g_temb);
  cudaGetSymbolAddress((void**)&p_feat, g_feat);
  cudaGetSymbolAddress((void**)&p_d1, g_d1);
  cudaGetSymbolAddress((void**)&p_d2, g_d2);
  cudaGetSymbolAddress((void**)&p_d3, g_d3);

  time_emb_kernel<<<BB, EE>>>(t, time_w1, time_b1, time_w2, time_b2);
  patch_gather_kernel<<<(NTOK*512)/256, 256>>>(x);
  patch_gemm<<<dim3(EE/64, NTOK/64), 128>>>(p_patches, patch_w, patch_b, pos, p_temb, p_h);

  for (int i=0;i<DEPTH;i++){
    inproj_ln_gemm<<<dim3(XZW/128, NTOK/128), 256>>>(in_proj + (size_t)i*XZW*EE,
                                                     ln_g + (size_t)i*EE, ln_b + (size_t)i*EE, p_xz);
    prep_kernel<<<NTOK/8, 256>>>(conv_w + (size_t)i*DI*DCN, conv_b + (size_t)i*DI,
                                 x_proj + (size_t)i*48*DI,
                                 dt_w + (size_t)i*DI*DTRN, dt_b + (size_t)i*DI);
    ssm_scan<<<BB*DI, 256>>>(A_log + (size_t)i*DI*DS, Dp + (size_t)i*DI);
    outproj_gemm<<<dim3(EE/64, NTOK/64), 128>>>(out_proj + (size_t)i*EE*DI);
  }

  feat_kernel<<<dim3(LL/32, EE/32, BB), dim3(32,8)>>>();
  convt_kernel<256,128,4,1><<<(BB*(128/4)*16*16)/256, 256>>>(p_feat, dw1, db1, p_d1, 16, 16);
  convt_kernel<128,64,4,1><<<(BB*(64/4)*32*32)/256, 256>>>(p_d1, dw2, db2, p_d2, 32, 32);
  convt_kernel<64,32,4,1><<<(BB*(32/4)*64*64)/256, 256>>>(p_d2, dw3, db3, p_d3, 64, 64);
  convt_kernel<32,1,1,0><<<(BB*1*128*128)/256, 256>>>(p_d3, dw4, db4, (float*)d_out, 128, 128);
}